// round 2
// baseline (speedup 1.0000x reference)
#include <cuda_runtime.h>
#include <math.h>

#define NMAX 32
#define PMAX 8732
#define OMAX 16

// Scratch (no allocations allowed)
__device__ unsigned long long g_pfo[NMAX * OMAX];   // packed (iou_bits<<32 | ~p) per (n,o)
__device__ float g_ovl[NMAX * PMAX];                // best overlap per prior
__device__ int   g_ofp[NMAX * PMAX];                // best object per prior
__device__ float g_ce_neg[NMAX * PMAX];             // CE of negatives (0 at positives)
__device__ int   g_npos[NMAX];
__device__ float g_sums[3];                         // 0: loc_sum, 1: ce_pos_sum, 2: hard_neg_sum

// ---------------------------------------------------------------------------
__global__ void k_init(int N, int O) {
    int i = blockIdx.x * blockDim.x + threadIdx.x;
    if (i < N * O) g_pfo[i] = 0ull;
    if (i < N) g_npos[i] = 0;
    if (i < 3) g_sums[i] = 0.0f;
}

// ---------------------------------------------------------------------------
// One thread per prior; block handles a chunk of priors for sample n = blockIdx.y.
__global__ void k_iou(const float* __restrict__ boxes,
                      const float* __restrict__ priors,
                      int N, int P, int O) {
    int n = blockIdx.y;
    int p = blockIdx.x * blockDim.x + threadIdx.x;
    __shared__ float sb[OMAX * 4];
    __shared__ unsigned long long sbest[OMAX];
    if (threadIdx.x < O * 4) sb[threadIdx.x] = boxes[(size_t)n * O * 4 + threadIdx.x];
    if (threadIdx.x < O) sbest[threadIdx.x] = 0ull;
    __syncthreads();

    bool act = (p < P);
    float px1 = 0.f, py1 = 0.f, px2 = 0.f, py2 = 0.f, pa = 0.f;
    if (act) {
        float4 pc = ((const float4*)priors)[p];   // cx cy w h
        px1 = pc.x - pc.z * 0.5f; py1 = pc.y - pc.w * 0.5f;
        px2 = pc.x + pc.z * 0.5f; py2 = pc.y + pc.w * 0.5f;
        pa  = pc.z * pc.w;
    }

    float bestv = -1.0f; int besto = 0;
    for (int o = 0; o < O; o++) {
        float v = 0.0f;
        if (act) {
            float bx1 = sb[o*4+0], by1 = sb[o*4+1], bx2 = sb[o*4+2], by2 = sb[o*4+3];
            float iw = fmaxf(fminf(px2, bx2) - fmaxf(px1, bx1), 0.0f);
            float ih = fmaxf(fminf(py2, by2) - fmaxf(py1, by1), 0.0f);
            float inter = iw * ih;
            float ba = (bx2 - bx1) * (by2 - by1);
            v = inter / (pa + ba - inter);
            if (v > bestv) { bestv = v; besto = o; }   // strict > => first occurrence
        }
        // argmax over P for this object: packed key, ties -> smallest p
        unsigned long long key = act
            ? ((((unsigned long long)__float_as_uint(v)) << 32) |
               (unsigned long long)(0xffffffffu - (unsigned)p))
            : 0ull;
        #pragma unroll
        for (int off = 16; off; off >>= 1) {
            unsigned long long other = __shfl_down_sync(0xffffffffu, key, off);
            if (other > key) key = other;
        }
        if ((threadIdx.x & 31) == 0) atomicMax(&sbest[o], key);
    }
    if (act) {
        g_ovl[(size_t)n * P + p] = bestv;
        g_ofp[(size_t)n * P + p] = besto;
    }
    __syncthreads();
    if (threadIdx.x < O) atomicMax(&g_pfo[n * O + threadIdx.x], sbest[threadIdx.x]);
}

// ---------------------------------------------------------------------------
// Force each object to its best prior (sequential per sample => last-wins in o order).
__global__ void k_force(int N, int P, int O) {
    int n = blockIdx.x * blockDim.x + threadIdx.x;
    if (n >= N) return;
    for (int o = 0; o < O; o++) {
        unsigned long long key = g_pfo[n * O + o];
        unsigned p = 0xffffffffu - (unsigned)(key & 0xffffffffu);
        g_ofp[(size_t)n * P + p] = o;
        g_ovl[(size_t)n * P + p] = 1.0f;
    }
}

// ---------------------------------------------------------------------------
// Warp per prior: log-softmax CE + loc loss for positives.
__global__ void k_main(const float* __restrict__ locs,
                       const float* __restrict__ scores,
                       const float* __restrict__ boxes,
                       const int*   __restrict__ labels,
                       const float* __restrict__ priors,
                       int N, int P, int O, int C) {
    int n = blockIdx.y;
    int warp = threadIdx.x >> 5, lane = threadIdx.x & 31;
    int p = blockIdx.x * (blockDim.x >> 5) + warp;

    __shared__ float s_loc, s_cep;
    __shared__ int s_np;
    if (threadIdx.x == 0) { s_loc = 0.0f; s_cep = 0.0f; s_np = 0; }
    __syncthreads();

    if (p < P) {
        const float* row = scores + ((size_t)n * P + p) * C;
        float m = -1e30f;
        for (int i = lane; i < C; i += 32) m = fmaxf(m, row[i]);
        #pragma unroll
        for (int off = 16; off; off >>= 1) m = fmaxf(m, __shfl_xor_sync(0xffffffffu, m, off));
        float s = 0.0f;
        for (int i = lane; i < C; i += 32) s += expf(row[i] - m);
        #pragma unroll
        for (int off = 16; off; off >>= 1) s += __shfl_xor_sync(0xffffffffu, s, off);

        if (lane == 0) {
            float lse = m + logf(s);
            size_t idx = (size_t)n * P + p;
            float ovl = g_ovl[idx];
            int o = g_ofp[idx];
            int lbl = labels[n * O + o];
            int tc = (ovl < 0.5f) ? 0 : lbl;
            float ce = lse - row[tc];
            bool pos = (tc != 0);
            g_ce_neg[idx] = pos ? 0.0f : ce;
            if (pos) {
                float4 b  = ((const float4*)boxes)[n * O + o];   // x1 y1 x2 y2
                float4 pr = ((const float4*)priors)[p];          // cx cy w h
                float cx = (b.x + b.z) * 0.5f, cy = (b.y + b.w) * 0.5f;
                float w = b.z - b.x, h = b.w - b.y;
                float g0 = (cx - pr.x) * 10.0f / pr.z;
                float g1 = (cy - pr.y) * 10.0f / pr.w;
                float g2 = logf(w / pr.z) * 5.0f;
                float g3 = logf(h / pr.w) * 5.0f;
                float4 pl = ((const float4*)locs)[idx];
                float l = fabsf(pl.x - g0) + fabsf(pl.y - g1) +
                          fabsf(pl.z - g2) + fabsf(pl.w - g3);
                atomicAdd(&s_loc, l);
                atomicAdd(&s_cep, ce);
                atomicAdd(&s_np, 1);
            }
        }
    }
    __syncthreads();
    if (threadIdx.x == 0 && s_np) {
        atomicAdd(&g_sums[0], s_loc);
        atomicAdd(&g_sums[1], s_cep);
        atomicAdd(&g_npos[n], s_np);
    }
}

// ---------------------------------------------------------------------------
// Per-sample bitonic sort (ascending) in shared, then sum top 3*n_pos.
__global__ void k_sortsum(int P, int M) {
    extern __shared__ float sh[];
    int n = blockIdx.x;
    for (int i = threadIdx.x; i < M; i += blockDim.x)
        sh[i] = (i < P) ? g_ce_neg[(size_t)n * P + i] : -1.0f;  // all real values >= 0
    __syncthreads();

    for (int k = 2; k <= M; k <<= 1) {
        for (int j = k >> 1; j > 0; j >>= 1) {
            for (int i = threadIdx.x; i < M; i += blockDim.x) {
                int ixj = i ^ j;
                if (ixj > i) {
                    float a = sh[i], b = sh[ixj];
                    bool up = ((i & k) == 0);
                    if ((a > b) == up) { sh[i] = b; sh[ixj] = a; }
                }
            }
            __syncthreads();
        }
    }

    int np = g_npos[n];
    int kk = 3 * np; if (kk > P) kk = P;
    float acc = 0.0f;
    for (int i = M - kk + threadIdx.x; i < M; i += blockDim.x) acc += sh[i];
    #pragma unroll
    for (int off = 16; off; off >>= 1) acc += __shfl_xor_sync(0xffffffffu, acc, off);
    __shared__ float sred[32];
    if ((threadIdx.x & 31) == 0) sred[threadIdx.x >> 5] = acc;
    __syncthreads();
    if (threadIdx.x < 32) {
        float v = (threadIdx.x < (blockDim.x >> 5)) ? sred[threadIdx.x] : 0.0f;
        #pragma unroll
        for (int off = 16; off; off >>= 1) v += __shfl_xor_sync(0xffffffffu, v, off);
        if (threadIdx.x == 0) atomicAdd(&g_sums[2], v);
    }
}

// ---------------------------------------------------------------------------
__global__ void k_final(float* __restrict__ out, int N) {
    int npt = 0;
    for (int i = 0; i < N; i++) npt += g_npos[i];
    float fn = (float)npt;
    float conf = (g_sums[2] + g_sums[1]) / fn;
    float loc  = g_sums[0] / (4.0f * fn);
    out[0] = conf + loc;
}

// ---------------------------------------------------------------------------
extern "C" void kernel_launch(void* const* d_in, const int* in_sizes, int n_in,
                              void* d_out, int out_size) {
    const float* locs   = (const float*)d_in[0];
    const float* scores = (const float*)d_in[1];
    const float* boxes  = (const float*)d_in[2];
    const int*   labels = (const int*)d_in[3];
    const float* priors = (const float*)d_in[4];

    int P = in_sizes[4] / 4;
    int N = in_sizes[0] / (4 * P);
    int C = in_sizes[1] / (N * P);
    int O = in_sizes[3] / N;

    // next power of two >= P for bitonic sort
    int M = 1;
    while (M < P) M <<= 1;
    size_t smem = (size_t)M * sizeof(float);
    cudaFuncSetAttribute(k_sortsum, cudaFuncAttributeMaxDynamicSharedMemorySize, (int)smem);

    k_init<<<(N * O + 255) / 256, 256>>>(N, O);

    dim3 giou((P + 255) / 256, N);
    k_iou<<<giou, 256>>>(boxes, priors, N, P, O);

    k_force<<<1, 32>>>(N, P, O);

    dim3 gmain((P + 7) / 8, N);   // 8 warps/block, warp per prior
    k_main<<<gmain, 256>>>(locs, scores, boxes, labels, priors, N, P, O, C);

    k_sortsum<<<N, 1024, smem>>>(P, M);

    k_final<<<1, 1>>>((float*)d_out, N);
}

// round 3
// speedup vs baseline: 2.0593x; 2.0593x over previous
#include <cuda_runtime.h>
#include <math.h>

#define NMAX 32
#define PMAX 8732
#define OMAX 16

// Scratch (no allocations allowed)
__device__ unsigned long long g_pfo[NMAX * OMAX];   // packed (iou_bits<<32 | ~p) per (n,o)
__device__ float g_ovl[NMAX * PMAX];                // best overlap per prior
__device__ int   g_ofp[NMAX * PMAX];                // best object per prior
__device__ float g_ce_neg[NMAX * PMAX];             // CE of negatives (0 at positives)
__device__ int   g_npos[NMAX];
__device__ float g_sums[3];                         // 0: loc_sum, 1: ce_pos_sum, 2: hard_neg_sum

// ---------------------------------------------------------------------------
__global__ void k_init(int N, int O) {
    int i = blockIdx.x * blockDim.x + threadIdx.x;
    if (i < N * O) g_pfo[i] = 0ull;
    if (i < N) g_npos[i] = 0;
    if (i < 3) g_sums[i] = 0.0f;
}

// ---------------------------------------------------------------------------
// One thread per prior; block handles a chunk of priors for sample n = blockIdx.y.
// Per-object argmax over P via REDUX + ballot (cheap) -> one shared atomic per warp.
__global__ void k_iou(const float* __restrict__ boxes,
                      const float* __restrict__ priors,
                      int N, int P, int O) {
    int n = blockIdx.y;
    int p = blockIdx.x * blockDim.x + threadIdx.x;
    int lane = threadIdx.x & 31;
    __shared__ float sb[OMAX * 4];
    __shared__ unsigned long long sbest[OMAX];
    if (threadIdx.x < O * 4) sb[threadIdx.x] = boxes[(size_t)n * O * 4 + threadIdx.x];
    if (threadIdx.x < O) sbest[threadIdx.x] = 0ull;
    __syncthreads();

    bool act = (p < P);
    float px1 = 0.f, py1 = 0.f, px2 = 0.f, py2 = 0.f, pa = 0.f;
    if (act) {
        float4 pc = ((const float4*)priors)[p];   // cx cy w h
        px1 = pc.x - pc.z * 0.5f; py1 = pc.y - pc.w * 0.5f;
        px2 = pc.x + pc.z * 0.5f; py2 = pc.y + pc.w * 0.5f;
        pa  = pc.z * pc.w;
    }

    float bestv = -1.0f; int besto = 0;
    #pragma unroll 4
    for (int o = 0; o < O; o++) {
        float v = 0.0f;
        if (act) {
            float bx1 = sb[o*4+0], by1 = sb[o*4+1], bx2 = sb[o*4+2], by2 = sb[o*4+3];
            float iw = fmaxf(fminf(px2, bx2) - fmaxf(px1, bx1), 0.0f);
            float ih = fmaxf(fminf(py2, by2) - fmaxf(py1, by1), 0.0f);
            float inter = iw * ih;
            float ba = (bx2 - bx1) * (by2 - by1);
            v = inter / (pa + ba - inter);
            if (v > bestv) { bestv = v; besto = o; }   // strict > => first occurrence
        }
        // argmax over P for this object (warp stage): iou >= 0 so float bits order = value order
        unsigned bits = act ? __float_as_uint(v) : 0u;
        unsigned maxb = __reduce_max_sync(0xffffffffu, act ? bits : 0u);
        unsigned ball = __ballot_sync(0xffffffffu, act && bits == maxb);
        if (ball && lane == (__ffs(ball) - 1)) {
            unsigned long long key = (((unsigned long long)maxb) << 32) |
                                     (unsigned long long)(0xffffffffu - (unsigned)p);
            atomicMax(&sbest[o], key);
        }
    }
    if (act) {
        g_ovl[(size_t)n * P + p] = bestv;
        g_ofp[(size_t)n * P + p] = besto;
    }
    __syncthreads();
    if (threadIdx.x < O) atomicMax(&g_pfo[n * O + threadIdx.x], sbest[threadIdx.x]);
}

// ---------------------------------------------------------------------------
// Force each object to its best prior (sequential per sample => last-wins in o order).
__global__ void k_force(int N, int P, int O) {
    int n = blockIdx.x * blockDim.x + threadIdx.x;
    if (n >= N) return;
    for (int o = 0; o < O; o++) {
        unsigned long long key = g_pfo[n * O + o];
        unsigned p = 0xffffffffu - (unsigned)(key & 0xffffffffu);
        g_ofp[(size_t)n * P + p] = o;
        g_ovl[(size_t)n * P + p] = 1.0f;
    }
}

// ---------------------------------------------------------------------------
// Warp per prior: log-softmax CE + loc loss for positives. Single load pass,
// hardware __expf/__logf.
__global__ void k_main(const float* __restrict__ locs,
                       const float* __restrict__ scores,
                       const float* __restrict__ boxes,
                       const int*   __restrict__ labels,
                       const float* __restrict__ priors,
                       int N, int P, int O, int C) {
    int n = blockIdx.y;
    int warp = threadIdx.x >> 5, lane = threadIdx.x & 31;
    int p = blockIdx.x * (blockDim.x >> 5) + warp;

    __shared__ float s_loc, s_cep;
    __shared__ int s_np;
    if (threadIdx.x == 0) { s_loc = 0.0f; s_cep = 0.0f; s_np = 0; }
    __syncthreads();

    if (p < P) {
        const float* row = scores + ((size_t)n * P + p) * C;
        float v[4];
        int cnt = 0;
        #pragma unroll 4
        for (int i = lane; i < C; i += 32) v[cnt++] = row[i];

        float m = -1e30f;
        #pragma unroll 4
        for (int j = 0; j < 4; j++) if (j < cnt) m = fmaxf(m, v[j]);
        #pragma unroll
        for (int off = 16; off; off >>= 1) m = fmaxf(m, __shfl_xor_sync(0xffffffffu, m, off));

        float s = 0.0f;
        #pragma unroll 4
        for (int j = 0; j < 4; j++) if (j < cnt) s += __expf(v[j] - m);
        #pragma unroll
        for (int off = 16; off; off >>= 1) s += __shfl_xor_sync(0xffffffffu, s, off);

        if (lane == 0) {
            float lse = m + __logf(s);
            size_t idx = (size_t)n * P + p;
            float ovl = g_ovl[idx];
            int o = g_ofp[idx];
            int lbl = labels[n * O + o];
            int tc = (ovl < 0.5f) ? 0 : lbl;
            float ce = lse - row[tc];
            bool pos = (tc != 0);
            g_ce_neg[idx] = pos ? 0.0f : ce;
            if (pos) {
                float4 b  = ((const float4*)boxes)[n * O + o];   // x1 y1 x2 y2
                float4 pr = ((const float4*)priors)[p];          // cx cy w h
                float cx = (b.x + b.z) * 0.5f, cy = (b.y + b.w) * 0.5f;
                float w = b.z - b.x, h = b.w - b.y;
                float g0 = (cx - pr.x) * 10.0f / pr.z;
                float g1 = (cy - pr.y) * 10.0f / pr.w;
                float g2 = __logf(w / pr.z) * 5.0f;
                float g3 = __logf(h / pr.w) * 5.0f;
                float4 pl = ((const float4*)locs)[idx];
                float l = fabsf(pl.x - g0) + fabsf(pl.y - g1) +
                          fabsf(pl.z - g2) + fabsf(pl.w - g3);
                atomicAdd(&s_loc, l);
                atomicAdd(&s_cep, ce);
                atomicAdd(&s_np, 1);
            }
        }
    }
    __syncthreads();
    if (threadIdx.x == 0 && s_np) {
        atomicAdd(&g_sums[0], s_loc);
        atomicAdd(&g_sums[1], s_cep);
        atomicAdd(&g_npos[n], s_np);
    }
}

// ---------------------------------------------------------------------------
// Per-sample exact top-K sum via 4-pass radix select on float bits (all values >= 0,
// so uint order == float order). K-th largest value t found exactly; then
// topK_sum = sum(bits > t_bits) + (K - count(bits > t_bits)) * t  (exact, ties equal t).
__global__ void k_topk(int P) {
    __shared__ float sh[PMAX];
    __shared__ unsigned hist[256];
    __shared__ unsigned s_prefix, s_kk;
    __shared__ float s_red[32];

    int n = blockIdx.x;
    int tid = threadIdx.x;
    int nthr = blockDim.x;

    for (int i = tid; i < P; i += nthr) sh[i] = g_ce_neg[(size_t)n * P + i];

    int np = g_npos[n];
    int K = 3 * np; if (K > P) K = P;
    if (tid == 0) { s_prefix = 0u; s_kk = (unsigned)K; }
    __syncthreads();
    if (K <= 0) return;

    for (int shift = 24; shift >= 0; shift -= 8) {
        if (tid < 256) hist[tid] = 0u;
        __syncthreads();
        unsigned prefix = s_prefix;
        unsigned hm = (shift == 24) ? 0u : (0xffffffffu << (shift + 8));
        for (int i = tid; i < P; i += nthr) {
            unsigned b = __float_as_uint(sh[i]);
            if ((b & hm) == prefix) atomicAdd(&hist[(b >> shift) & 255u], 1u);
        }
        __syncthreads();
        if (tid == 0) {
            unsigned kk = s_kk, acc = 0; int bin = 255;
            for (; bin >= 0; bin--) { acc += hist[bin]; if (acc >= kk) break; }
            if (bin < 0) bin = 0;                      // safety
            s_prefix = prefix | ((unsigned)bin << shift);
            s_kk = kk - (acc - hist[bin]);
        }
        __syncthreads();
    }

    unsigned tbits = s_prefix;
    float tval = __uint_as_float(tbits);

    float sum = 0.0f; unsigned cnt = 0;
    for (int i = tid; i < P; i += nthr) {
        unsigned b = __float_as_uint(sh[i]);
        if (b > tbits) { sum += sh[i]; cnt++; }
    }
    float fc = (float)cnt;
    #pragma unroll
    for (int off = 16; off; off >>= 1) {
        sum += __shfl_xor_sync(0xffffffffu, sum, off);
        fc  += __shfl_xor_sync(0xffffffffu, fc, off);
    }
    if ((tid & 31) == 0) { s_red[tid >> 5] = sum; hist[tid >> 5] = (unsigned)fc; }
    __syncthreads();
    if (tid < 32) {
        int nw = nthr >> 5;
        float v = (tid < nw) ? s_red[tid] : 0.0f;
        float c = (tid < nw) ? (float)hist[tid] : 0.0f;
        #pragma unroll
        for (int off = 16; off; off >>= 1) {
            v += __shfl_xor_sync(0xffffffffu, v, off);
            c += __shfl_xor_sync(0xffffffffu, c, off);
        }
        if (tid == 0) {
            float total = v + ((float)K - c) * tval;
            atomicAdd(&g_sums[2], total);
        }
    }
}

// ---------------------------------------------------------------------------
__global__ void k_final(float* __restrict__ out, int N) {
    int npt = 0;
    for (int i = 0; i < N; i++) npt += g_npos[i];
    float fn = (float)npt;
    float conf = (g_sums[2] + g_sums[1]) / fn;
    float loc  = g_sums[0] / (4.0f * fn);
    out[0] = conf + loc;
}

// ---------------------------------------------------------------------------
extern "C" void kernel_launch(void* const* d_in, const int* in_sizes, int n_in,
                              void* d_out, int out_size) {
    const float* locs   = (const float*)d_in[0];
    const float* scores = (const float*)d_in[1];
    const float* boxes  = (const float*)d_in[2];
    const int*   labels = (const int*)d_in[3];
    const float* priors = (const float*)d_in[4];

    int P = in_sizes[4] / 4;
    int N = in_sizes[0] / (4 * P);
    int C = in_sizes[1] / (N * P);
    int O = in_sizes[3] / N;

    k_init<<<(N * O + 255) / 256, 256>>>(N, O);

    dim3 giou((P + 255) / 256, N);
    k_iou<<<giou, 256>>>(boxes, priors, N, P, O);

    k_force<<<1, 32>>>(N, P, O);

    dim3 gmain((P + 15) / 16, N);   // 16 warps/block, warp per prior
    k_main<<<gmain, 512>>>(locs, scores, boxes, labels, priors, N, P, O, C);

    k_topk<<<N, 512>>>(P);

    k_final<<<1, 1>>>((float*)d_out, N);
}

// round 4
// speedup vs baseline: 3.6022x; 1.7492x over previous
#include <cuda_runtime.h>
#include <math.h>

#define NMAX 32
#define PMAX 8732
#define OMAX 16
#define ROWS_PER_BLK 128

// Scratch (no allocations allowed)
__device__ unsigned long long g_pfo[NMAX * OMAX];   // packed (iou_bits<<32 | ~p) per (n,o)
__device__ float g_ovl[NMAX * PMAX];                // best overlap per prior
__device__ int   g_ofp[NMAX * PMAX];                // best object per prior
__device__ float g_ce_neg[NMAX * PMAX];             // CE of negatives (0 at positives)
__device__ int   g_npos[NMAX];
__device__ float g_sums[3];                         // 0: loc_sum, 1: ce_pos_sum, 2: hard_neg_sum

// ---------------------------------------------------------------------------
__global__ void k_init(int N, int O) {
    int i = blockIdx.x * blockDim.x + threadIdx.x;
    if (i < N * O) g_pfo[i] = 0ull;
    if (i < N) g_npos[i] = 0;
    if (i < 3) g_sums[i] = 0.0f;
}

// ---------------------------------------------------------------------------
// One thread per prior; block handles a chunk of priors for sample n = blockIdx.y.
__global__ void k_iou(const float* __restrict__ boxes,
                      const float* __restrict__ priors,
                      int N, int P, int O) {
    int n = blockIdx.y;
    int p = blockIdx.x * blockDim.x + threadIdx.x;
    int lane = threadIdx.x & 31;
    __shared__ float sb[OMAX * 4];
    __shared__ unsigned long long sbest[OMAX];
    if (threadIdx.x < O * 4) sb[threadIdx.x] = boxes[(size_t)n * O * 4 + threadIdx.x];
    if (threadIdx.x < O) sbest[threadIdx.x] = 0ull;
    __syncthreads();

    bool act = (p < P);
    float px1 = 0.f, py1 = 0.f, px2 = 0.f, py2 = 0.f, pa = 0.f;
    if (act) {
        float4 pc = ((const float4*)priors)[p];   // cx cy w h
        px1 = pc.x - pc.z * 0.5f; py1 = pc.y - pc.w * 0.5f;
        px2 = pc.x + pc.z * 0.5f; py2 = pc.y + pc.w * 0.5f;
        pa  = pc.z * pc.w;
    }

    float bestv = -1.0f; int besto = 0;
    #pragma unroll 4
    for (int o = 0; o < O; o++) {
        float v = 0.0f;
        if (act) {
            float bx1 = sb[o*4+0], by1 = sb[o*4+1], bx2 = sb[o*4+2], by2 = sb[o*4+3];
            float iw = fmaxf(fminf(px2, bx2) - fmaxf(px1, bx1), 0.0f);
            float ih = fmaxf(fminf(py2, by2) - fmaxf(py1, by1), 0.0f);
            float inter = iw * ih;
            float ba = (bx2 - bx1) * (by2 - by1);
            v = inter / (pa + ba - inter);
            if (v > bestv) { bestv = v; besto = o; }   // strict > => first occurrence
        }
        // argmax over P for this object: iou >= 0 so float-bit order == value order
        unsigned bits = act ? __float_as_uint(v) : 0u;
        unsigned maxb = __reduce_max_sync(0xffffffffu, bits);
        unsigned ball = __ballot_sync(0xffffffffu, act && bits == maxb);
        if (ball && lane == (__ffs(ball) - 1)) {
            unsigned long long key = (((unsigned long long)maxb) << 32) |
                                     (unsigned long long)(0xffffffffu - (unsigned)p);
            atomicMax(&sbest[o], key);
        }
    }
    if (act) {
        g_ovl[(size_t)n * P + p] = bestv;
        g_ofp[(size_t)n * P + p] = besto;
    }
    __syncthreads();
    if (threadIdx.x < O) atomicMax(&g_pfo[n * O + threadIdx.x], sbest[threadIdx.x]);
}

// ---------------------------------------------------------------------------
// Force each object to its best prior (sequential per sample => last-wins in o order).
__global__ void k_force(int N, int P, int O) {
    int n = blockIdx.x * blockDim.x + threadIdx.x;
    if (n >= N) return;
    for (int o = 0; o < O; o++) {
        unsigned long long key = g_pfo[n * O + o];
        unsigned p = 0xffffffffu - (unsigned)(key & 0xffffffffu);
        g_ofp[(size_t)n * P + p] = o;
        g_ovl[(size_t)n * P + p] = 1.0f;
    }
}

// ---------------------------------------------------------------------------
// Thread-per-prior with shared staging: block loads 128 contiguous score rows
// coalesced (float4), each thread reduces its own row from shared.
// Stride-81 row access is bank-conflict-free (81 odd).
template<int CT>
__global__ void k_main_t(const float* __restrict__ locs,
                         const float* __restrict__ scores,
                         const float* __restrict__ boxes,
                         const int*   __restrict__ labels,
                         const float* __restrict__ priors,
                         int N, int P, int O, int Crt) {
    const int C = (CT > 0) ? CT : Crt;
    __shared__ float sh[ROWS_PER_BLK * 81];   // CT==81 path; generic path guarded below
    __shared__ float s_loc, s_cep;
    __shared__ int s_np;

    int n = blockIdx.y;
    int r0 = blockIdx.x * ROWS_PER_BLK;
    int rows = P - r0; if (rows > ROWS_PER_BLK) rows = ROWS_PER_BLK;
    int elems = rows * C;
    const float* base = scores + ((size_t)n * P + r0) * C;

    if (threadIdx.x == 0) { s_loc = 0.0f; s_cep = 0.0f; s_np = 0; }

    // Coalesced float4 staging (base is 16B aligned: offsets are multiples of 4 floats)
    int e4 = elems >> 2;
    const float4* b4 = (const float4*)base;
    for (int i = threadIdx.x; i < e4; i += blockDim.x)
        ((float4*)sh)[i] = b4[i];
    for (int i = (e4 << 2) + threadIdx.x; i < elems; i += blockDim.x)
        sh[i] = base[i];
    __syncthreads();

    int p = r0 + threadIdx.x;
    if (threadIdx.x < rows) {
        const float* row = sh + threadIdx.x * C;

        float m = row[0];
        #pragma unroll
        for (int i = 1; i < C; i++) m = fmaxf(m, row[i]);
        float s = 0.0f;
        #pragma unroll
        for (int i = 0; i < C; i++) s += __expf(row[i] - m);
        float lse = m + __logf(s);

        size_t idx = (size_t)n * P + p;
        float ovl = g_ovl[idx];
        int o = g_ofp[idx];
        int lbl = labels[n * O + o];
        int tc = (ovl < 0.5f) ? 0 : lbl;
        float ce = lse - row[tc];
        bool pos = (tc != 0);
        g_ce_neg[idx] = pos ? 0.0f : ce;
        if (pos) {
            float4 b  = ((const float4*)boxes)[n * O + o];   // x1 y1 x2 y2
            float4 pr = ((const float4*)priors)[p];          // cx cy w h
            float cx = (b.x + b.z) * 0.5f, cy = (b.y + b.w) * 0.5f;
            float w = b.z - b.x, h = b.w - b.y;
            float g0 = (cx - pr.x) * 10.0f / pr.z;
            float g1 = (cy - pr.y) * 10.0f / pr.w;
            float g2 = __logf(w / pr.z) * 5.0f;
            float g3 = __logf(h / pr.w) * 5.0f;
            float4 pl = ((const float4*)locs)[idx];
            float l = fabsf(pl.x - g0) + fabsf(pl.y - g1) +
                      fabsf(pl.z - g2) + fabsf(pl.w - g3);
            atomicAdd(&s_loc, l);
            atomicAdd(&s_cep, ce);
            atomicAdd(&s_np, 1);
        }
    }
    __syncthreads();
    if (threadIdx.x == 0 && s_np) {
        atomicAdd(&g_sums[0], s_loc);
        atomicAdd(&g_sums[1], s_cep);
        atomicAdd(&g_npos[n], s_np);
    }
}

// ---------------------------------------------------------------------------
// Per-sample exact top-K sum via 4-pass radix select on float bits (values >= 0).
__global__ void k_topk(int P) {
    __shared__ float sh[PMAX];
    __shared__ unsigned hist[256];
    __shared__ unsigned s_prefix, s_kk;
    __shared__ float s_red[32];

    int n = blockIdx.x;
    int tid = threadIdx.x;
    int nthr = blockDim.x;

    for (int i = tid; i < P; i += nthr) sh[i] = g_ce_neg[(size_t)n * P + i];

    int np = g_npos[n];
    int K = 3 * np; if (K > P) K = P;
    if (tid == 0) { s_prefix = 0u; s_kk = (unsigned)K; }
    __syncthreads();
    if (K <= 0) return;

    for (int shift = 24; shift >= 0; shift -= 8) {
        if (tid < 256) hist[tid] = 0u;
        __syncthreads();
        unsigned prefix = s_prefix;
        unsigned hm = (shift == 24) ? 0u : (0xffffffffu << (shift + 8));
        for (int i = tid; i < P; i += nthr) {
            unsigned b = __float_as_uint(sh[i]);
            if ((b & hm) == prefix) atomicAdd(&hist[(b >> shift) & 255u], 1u);
        }
        __syncthreads();
        if (tid == 0) {
            unsigned kk = s_kk, acc = 0; int bin = 255;
            for (; bin >= 0; bin--) { acc += hist[bin]; if (acc >= kk) break; }
            if (bin < 0) bin = 0;
            s_prefix = prefix | ((unsigned)bin << shift);
            s_kk = kk - (acc - hist[bin]);
        }
        __syncthreads();
    }

    unsigned tbits = s_prefix;
    float tval = __uint_as_float(tbits);

    float sum = 0.0f; unsigned cnt = 0;
    for (int i = tid; i < P; i += nthr) {
        unsigned b = __float_as_uint(sh[i]);
        if (b > tbits) { sum += sh[i]; cnt++; }
    }
    float fc = (float)cnt;
    #pragma unroll
    for (int off = 16; off; off >>= 1) {
        sum += __shfl_xor_sync(0xffffffffu, sum, off);
        fc  += __shfl_xor_sync(0xffffffffu, fc, off);
    }
    if ((tid & 31) == 0) { s_red[tid >> 5] = sum; hist[tid >> 5] = (unsigned)fc; }
    __syncthreads();
    if (tid < 32) {
        int nw = nthr >> 5;
        float v = (tid < nw) ? s_red[tid] : 0.0f;
        float c = (tid < nw) ? (float)hist[tid] : 0.0f;
        #pragma unroll
        for (int off = 16; off; off >>= 1) {
            v += __shfl_xor_sync(0xffffffffu, v, off);
            c += __shfl_xor_sync(0xffffffffu, c, off);
        }
        if (tid == 0) {
            float total = v + ((float)K - c) * tval;
            atomicAdd(&g_sums[2], total);
        }
    }
}

// ---------------------------------------------------------------------------
__global__ void k_final(float* __restrict__ out, int N) {
    int npt = 0;
    for (int i = 0; i < N; i++) npt += g_npos[i];
    float fn = (float)npt;
    float conf = (g_sums[2] + g_sums[1]) / fn;
    float loc  = g_sums[0] / (4.0f * fn);
    out[0] = conf + loc;
}

// ---------------------------------------------------------------------------
extern "C" void kernel_launch(void* const* d_in, const int* in_sizes, int n_in,
                              void* d_out, int out_size) {
    const float* locs   = (const float*)d_in[0];
    const float* scores = (const float*)d_in[1];
    const float* boxes  = (const float*)d_in[2];
    const int*   labels = (const int*)d_in[3];
    const float* priors = (const float*)d_in[4];

    int P = in_sizes[4] / 4;
    int N = in_sizes[0] / (4 * P);
    int C = in_sizes[1] / (N * P);
    int O = in_sizes[3] / N;

    k_init<<<(N * O + 255) / 256, 256>>>(N, O);

    dim3 giou((P + 255) / 256, N);
    k_iou<<<giou, 256>>>(boxes, priors, N, P, O);

    k_force<<<1, 32>>>(N, P, O);

    dim3 gmain((P + ROWS_PER_BLK - 1) / ROWS_PER_BLK, N);
    if (C == 81)
        k_main_t<81><<<gmain, ROWS_PER_BLK>>>(locs, scores, boxes, labels, priors, N, P, O, C);
    else if (C <= 81)
        k_main_t<0><<<gmain, ROWS_PER_BLK>>>(locs, scores, boxes, labels, priors, N, P, O, C);

    k_topk<<<N, 512>>>(P);

    k_final<<<1, 1>>>((float*)d_out, N);
}